// round 7
// baseline (speedup 1.0000x reference)
#include <cuda_runtime.h>
#include <cuda_bf16.h>
#include <cstdint>

// Problem dims
#define B_  16
#define T_  1024
#define DM  256
#define H_  4
#define HS  64
#define BT  (B_*T_)    // 16384
#define BH  (B_*H_)    // 64

typedef unsigned int u32;
typedef __nv_bfloat16 bf16;

// ---------------- scratch (device globals: allocation-free rule) ----------------
__device__ __align__(256) bf16 g_x [BT*DM];          // LN output
__device__ __align__(256) bf16 g_pe[BT*DM];          // pos_enc bf16
__device__ __align__(256) bf16 g_Wt[5][DM*DM];       // transposed weights [n][k]: q,k,v,p,o
__device__ __align__(256) bf16 g_qu[BH*T_*HS];       // q + bq + pos_bias_u, [b,h,t,s]
__device__ __align__(256) bf16 g_qv[BH*T_*HS];       // q + bq + pos_bias_v
__device__ __align__(256) bf16 g_kk[BH*T_*HS];
__device__ __align__(256) bf16 g_pp[BH*T_*HS];       // pos projection
__device__ __align__(256) bf16 g_vt[BH*HS*T_];       // V transposed [b,h,s,t]
__device__ __align__(256) bf16 g_P [BH*(long)T_*T_]; // pre-shift pos scores (128 MB)
__device__ __align__(256) bf16 g_ao[BT*DM];          // attention output, [b*T+t, h*HS+s]

// ---------------- helpers ----------------
__device__ __forceinline__ u32 ld32(const bf16* p) {
    return *reinterpret_cast<const u32*>(p);
}
__device__ __forceinline__ u32 packbf(float lo, float hi) {
    __nv_bfloat162 v = __floats2bfloat162_rn(lo, hi);
    return *reinterpret_cast<u32*>(&v);
}
// mma.sync m16n8k16 row.col f32 += bf16*bf16
__device__ __forceinline__ void mma16816(float* c, const u32* a, const u32* b) {
    asm volatile(
        "mma.sync.aligned.m16n8k16.row.col.f32.bf16.bf16.f32 "
        "{%0,%1,%2,%3}, {%4,%5,%6,%7}, {%8,%9}, {%0,%1,%2,%3};\n"
        : "+f"(c[0]), "+f"(c[1]), "+f"(c[2]), "+f"(c[3])
        : "r"(a[0]), "r"(a[1]), "r"(a[2]), "r"(a[3]), "r"(b[0]), "r"(b[1]));
}
__device__ __forceinline__ void cpasync16(void* smem, const void* gmem) {
    u32 sa = (u32)__cvta_generic_to_shared(smem);
    asm volatile("cp.async.cg.shared.global [%0], [%1], 16;\n" :: "r"(sa), "l"(gmem));
}
#define CP_COMMIT() asm volatile("cp.async.commit_group;\n")
#define CP_WAIT(n)  asm volatile("cp.async.wait_group %0;\n" :: "n"(n))

// ---------------- K0a: LayerNorm -> g_x (bf16) ----------------
__global__ void ln_kernel(const float* __restrict__ in,
                          const float* __restrict__ gamma,
                          const float* __restrict__ beta) {
    int row  = blockIdx.x * 8 + (threadIdx.x >> 5);
    int lane = threadIdx.x & 31;
    const float* r = in + (size_t)row * DM;
    float v[8];
    float s = 0.f;
#pragma unroll
    for (int i = 0; i < 8; i++) { v[i] = r[lane + 32*i]; s += v[i]; }
#pragma unroll
    for (int o = 16; o; o >>= 1) s += __shfl_xor_sync(0xffffffffu, s, o);
    float mu = s * (1.0f / DM);
    float vs = 0.f;
#pragma unroll
    for (int i = 0; i < 8; i++) { float d = v[i] - mu; vs += d * d; }
#pragma unroll
    for (int o = 16; o; o >>= 1) vs += __shfl_xor_sync(0xffffffffu, vs, o);
    float rstd = rsqrtf(vs * (1.0f / DM) + 1e-3f);
#pragma unroll
    for (int i = 0; i < 8; i++) {
        int c = lane + 32*i;
        g_x[(size_t)row*DM + c] =
            __float2bfloat16((v[i] - mu) * rstd * gamma[c] + beta[c]);
    }
}

// ---------------- K0b: pos_enc -> bf16 ----------------
__global__ void cvt_pe_kernel(const float* __restrict__ pe) {
    int i = blockIdx.x * blockDim.x + threadIdx.x;
    if (i < BT*DM) g_pe[i] = __float2bfloat16(pe[i]);
}

// ---------------- K0c: transpose+cvt the 5 weight matrices ----------------
__global__ void wt_kernel(const float* __restrict__ Wq, const float* __restrict__ Wk,
                          const float* __restrict__ Wv, const float* __restrict__ Wp,
                          const float* __restrict__ Wo) {
    int idx = blockIdx.x * blockDim.x + threadIdx.x;
    if (idx >= 5*DM*DM) return;
    int w = idx >> 16;
    int e = idx & 65535;
    int n = e >> 8, k = e & 255;
    const float* src = (w==0) ? Wq : (w==1) ? Wk : (w==2) ? Wv : (w==3) ? Wp : Wo;
    g_Wt[w][n*DM + k] = __float2bfloat16(src[k*DM + n]);
}

// ---------------- K1: projection GEMM (q/k/v/p), double-buffered smem ----------------
// grid (BT/128, 256/128, 4), block 256 (8 warps, 4x2 warp grid, warp tile 32x64)
#define KCH 64
#define LDA 72
#define GEMM_SMEM (4 * 128 * LDA * 2)   // As[2]+Bs[2], 73728 bytes
__global__ __launch_bounds__(256) void proj_kernel(
    const float* __restrict__ bq, const float* __restrict__ bk,
    const float* __restrict__ bv, const float* __restrict__ pbu,
    const float* __restrict__ pbv) {
    extern __shared__ __align__(16) bf16 dsm[];
    bf16 (*As)[LDA] = reinterpret_cast<bf16(*)[LDA]>(dsm);                 // [2*128][LDA]
    bf16 (*Bs)[LDA] = reinterpret_cast<bf16(*)[LDA]>(dsm + 2*128*LDA);
    int which = blockIdx.z;
    int m0 = blockIdx.x * 128, n0 = blockIdx.y * 128;
    const bf16* A = (which == 3) ? g_pe : g_x;
    const bf16* W = g_Wt[which];
    int tid = threadIdx.x;
    int wid = tid >> 5, lane = tid & 31;
    int wm = wid & 3, wn = wid >> 2;
    int g = lane >> 2, tg = lane & 3;

    auto stage = [&](int buf, int k0) {
#pragma unroll
        for (int i = 0; i < 4; i++) {
            int cid = tid + 256*i;
            int row = cid >> 3, seg = cid & 7;
            cpasync16(&As[buf*128 + row][seg*8], A + (size_t)(m0 + row)*DM + k0 + seg*8);
            cpasync16(&Bs[buf*128 + row][seg*8], W + (size_t)(n0 + row)*DM + k0 + seg*8);
        }
        CP_COMMIT();
    };

    float acc[2][8][4] = {};
    stage(0, 0);
    for (int c = 0; c < DM/KCH; c++) {
        if (c + 1 < DM/KCH) { stage((c+1) & 1, (c+1)*KCH); CP_WAIT(1); }
        else                { CP_WAIT(0); }
        __syncthreads();
        int bo_ = (c & 1) * 128;
#pragma unroll
        for (int ks = 0; ks < KCH/16; ks++) {
            u32 a[2][4];
#pragma unroll
            for (int mt = 0; mt < 2; mt++) {
                int rb = bo_ + wm*32 + mt*16 + g;
                a[mt][0] = ld32(&As[rb  ][ks*16 + 2*tg]);
                a[mt][1] = ld32(&As[rb+8][ks*16 + 2*tg]);
                a[mt][2] = ld32(&As[rb  ][ks*16 + 8 + 2*tg]);
                a[mt][3] = ld32(&As[rb+8][ks*16 + 8 + 2*tg]);
            }
#pragma unroll
            for (int nt = 0; nt < 8; nt++) {
                int nb = bo_ + wn*64 + nt*8 + g;
                u32 b[2];
                b[0] = ld32(&Bs[nb][ks*16 + 2*tg]);
                b[1] = ld32(&Bs[nb][ks*16 + 8 + 2*tg]);
                mma16816(acc[0][nt], a[0], b);
                mma16816(acc[1][nt], a[1], b);
            }
        }
        __syncthreads();
    }
#pragma unroll
    for (int mt = 0; mt < 2; mt++)
#pragma unroll
    for (int nt = 0; nt < 8; nt++)
#pragma unroll
    for (int e = 0; e < 4; e++) {
        int rr = m0 + wm*32 + mt*16 + g + ((e >= 2) ? 8 : 0);
        int cc = n0 + wn*64 + nt*8 + 2*tg + (e & 1);
        float val = acc[mt][nt][e];
        int b = rr >> 10, t = rr & (T_-1);
        int h = cc >> 6,  s = cc & (HS-1);
        long o = ((long)(b*H_ + h)*T_ + t)*HS + s;
        if (which == 0) {
            float q = val + bq[cc];
            g_qu[o] = __float2bfloat16(q + pbu[cc]);
            g_qv[o] = __float2bfloat16(q + pbv[cc]);
        } else if (which == 1) {
            g_kk[o] = __float2bfloat16(val + bk[cc]);
        } else if (which == 2) {
            g_vt[((long)(b*H_ + h)*HS + s)*T_ + t] = __float2bfloat16(val + bv[cc]);
        } else {
            g_pp[o] = __float2bfloat16(val);
        }
    }
}

// ---------------- K2: pre-shift pos scores P[bh] = qv @ pp^T, smem-staged ----------------
// grid (T/128, T/128, BH), block 256; K=64 single chunk
#define SPAD 8
__global__ __launch_bounds__(256) void pos_kernel() {
    __shared__ __align__(16) bf16 As[128][KCH + SPAD];
    __shared__ __align__(16) bf16 Bs[128][KCH + SPAD];
    int bh = blockIdx.z;
    int m0 = blockIdx.x * 128, n0 = blockIdx.y * 128;
    const bf16* A = g_qv + (long)bh * T_ * HS;
    const bf16* Bm = g_pp + (long)bh * T_ * HS;
    bf16* out = g_P + (long)bh * T_ * T_;
    int tid = threadIdx.x;
    int wid = tid >> 5, lane = tid & 31;
    int wm = wid & 3, wn = wid >> 2;
    int g = lane >> 2, tg = lane & 3;

#pragma unroll
    for (int i = 0; i < 4; i++) {
        int cid = tid + 256*i;
        int row = cid >> 3, seg = cid & 7;
        cpasync16(&As[row][seg*8], A + (long)(m0 + row)*HS + seg*8);
        cpasync16(&Bs[row][seg*8], Bm + (long)(n0 + row)*HS + seg*8);
    }
    CP_COMMIT(); CP_WAIT(0);
    __syncthreads();

    float acc[2][8][4] = {};
#pragma unroll
    for (int ks = 0; ks < 4; ks++) {
        u32 a[2][4];
#pragma unroll
        for (int mt = 0; mt < 2; mt++) {
            int rb = wm*32 + mt*16 + g;
            a[mt][0] = ld32(&As[rb  ][ks*16 + 2*tg]);
            a[mt][1] = ld32(&As[rb+8][ks*16 + 2*tg]);
            a[mt][2] = ld32(&As[rb  ][ks*16 + 8 + 2*tg]);
            a[mt][3] = ld32(&As[rb+8][ks*16 + 8 + 2*tg]);
        }
#pragma unroll
        for (int nt = 0; nt < 8; nt++) {
            int nb = wn*64 + nt*8 + g;
            u32 b[2];
            b[0] = ld32(&Bs[nb][ks*16 + 2*tg]);
            b[1] = ld32(&Bs[nb][ks*16 + 8 + 2*tg]);
            mma16816(acc[0][nt], a[0], b);
            mma16816(acc[1][nt], a[1], b);
        }
    }
    // packed u32 stores (pairs of consecutive cols)
#pragma unroll
    for (int mt = 0; mt < 2; mt++)
#pragma unroll
    for (int nt = 0; nt < 8; nt++) {
        int rr = m0 + wm*32 + mt*16 + g;
        int cc = n0 + wn*64 + nt*8 + 2*tg;
        *reinterpret_cast<u32*>(out + (long)rr*T_ + cc)     = packbf(acc[mt][nt][0], acc[mt][nt][1]);
        *reinterpret_cast<u32*>(out + (long)(rr+8)*T_ + cc) = packbf(acc[mt][nt][2], acc[mt][nt][3]);
    }
}

// ---------------- K3: flash attention, 128-row q-tile, K/V smem double-buffered ----------------
// grid (T/128, BH), block 256 (8 warps x 16 query rows)
// shift(P)[m,n] = (n==m+1) ? 0 : P_flat[m*T + (T-1-m) + n - (n>m)]
__global__ __launch_bounds__(256) void attn_kernel() {
    __shared__ __align__(16) bf16 Ks[2][64][72];
    __shared__ __align__(16) bf16 Vs[2][64][72];
    int bh = blockIdx.y;
    int m0 = blockIdx.x * 128;
    int tid = threadIdx.x;
    int wid = tid >> 5, lane = tid & 31;
    int g = lane >> 2, tg = lane & 3;
    const bf16* Qu = g_qu + (long)bh * T_ * HS;
    const bf16* K  = g_kk + (long)bh * T_ * HS;
    const bf16* Vt = g_vt + (long)bh * HS * T_;
    const bf16* Pm = g_P  + (long)bh * T_ * T_;
    int r0 = m0 + wid*16 + g;

    // persistent QU fragments
    u32 aq[4][4];
#pragma unroll
    for (int kk = 0; kk < 4; kk++) {
        aq[kk][0] = ld32(Qu + (long) r0   *HS + kk*16     + 2*tg);
        aq[kk][1] = ld32(Qu + (long)(r0+8)*HS + kk*16     + 2*tg);
        aq[kk][2] = ld32(Qu + (long) r0   *HS + kk*16 + 8 + 2*tg);
        aq[kk][3] = ld32(Qu + (long)(r0+8)*HS + kk*16 + 8 + 2*tg);
    }

    // stage(buf, n0): K rows [n0..n0+64) x 64 cols; Vt rows (s) 0..64 x cols [n0..n0+64)
    // 64 rows x 8 seg16 = 512 cp16 per matrix; 256 threads -> 2 iterations
    auto stage = [&](int buf, int n0) {
#pragma unroll
        for (int i = 0; i < 2; i++) {
            int cid = tid + 256*i;
            int row = cid >> 3, seg = cid & 7;   // row 0..63, seg 0..7 (16B = 8 bf16)
            cpasync16(&Ks[buf][row][seg*8], K  + (long)(n0 + row)*HS + seg*8);
            cpasync16(&Vs[buf][row][seg*8], Vt + (long)row*T_ + n0 + seg*8);
        }
        CP_COMMIT();
    };

    float mrow0 = -1e30f, mrow1 = -1e30f;
    float rsum0 = 0.f, rsum1 = 0.f;
    float o[8][4] = {};

    stage(0, 0);
    for (int it = 0; it < T_/64; it++) {
        int n0 = it * 64;
        int buf = it & 1;
        if (it + 1 < T_/64) { stage(buf ^ 1, n0 + 64); CP_WAIT(1); }
        else                { CP_WAIT(0); }
        __syncthreads();

        // S = QU @ K^T
        float s[8][4] = {};
#pragma unroll
        for (int kk = 0; kk < 4; kk++)
#pragma unroll
        for (int j = 0; j < 8; j++) {
            u32 b[2];
            b[0] = ld32(&Ks[buf][8*j + g][kk*16     + 2*tg]);
            b[1] = ld32(&Ks[buf][8*j + g][kk*16 + 8 + 2*tg]);
            mma16816(s[j], aq[kk], b);
        }
        // add shifted pos scores, scale
#pragma unroll
        for (int j = 0; j < 8; j++)
#pragma unroll
        for (int e = 0; e < 4; e++) {
            int rr = r0 + ((e >= 2) ? 8 : 0);
            int nn = n0 + 8*j + 2*tg + (e & 1);
            float pos = 0.f;
            if (nn != rr + 1) {
                long idx = (long)rr*T_ + (T_ - 1 - rr) + nn - (nn > rr ? 1 : 0);
                pos = __bfloat162float(Pm[idx]);
            }
            s[j][e] = (s[j][e] + pos) * 0.125f;
        }
        // online softmax
        float lm0 = -1e30f, lm1 = -1e30f;
#pragma unroll
        for (int j = 0; j < 8; j++) {
            lm0 = fmaxf(lm0, fmaxf(s[j][0], s[j][1]));
            lm1 = fmaxf(lm1, fmaxf(s[j][2], s[j][3]));
        }
        lm0 = fmaxf(lm0, __shfl_xor_sync(0xffffffffu, lm0, 1));
        lm0 = fmaxf(lm0, __shfl_xor_sync(0xffffffffu, lm0, 2));
        lm1 = fmaxf(lm1, __shfl_xor_sync(0xffffffffu, lm1, 1));
        lm1 = fmaxf(lm1, __shfl_xor_sync(0xffffffffu, lm1, 2));
        float nm0 = fmaxf(mrow0, lm0), nm1 = fmaxf(mrow1, lm1);
        float c0 = __expf(mrow0 - nm0), c1 = __expf(mrow1 - nm1);
        mrow0 = nm0; mrow1 = nm1;

        u32 pa[4][4];
        float ls0 = 0.f, ls1 = 0.f;
#pragma unroll
        for (int j = 0; j < 8; j++) {
            float p0 = __expf(s[j][0] - nm0);
            float p1 = __expf(s[j][1] - nm0);
            float p2 = __expf(s[j][2] - nm1);
            float p3 = __expf(s[j][3] - nm1);
            ls0 += p0 + p1; ls1 += p2 + p3;
            pa[j >> 1][(j & 1) ? 2 : 0] = packbf(p0, p1);
            pa[j >> 1][(j & 1) ? 3 : 1] = packbf(p2, p3);
        }
        ls0 += __shfl_xor_sync(0xffffffffu, ls0, 1);
        ls0 += __shfl_xor_sync(0xffffffffu, ls0, 2);
        ls1 += __shfl_xor_sync(0xffffffffu, ls1, 1);
        ls1 += __shfl_xor_sync(0xffffffffu, ls1, 2);
        rsum0 = rsum0 * c0 + ls0;
        rsum1 = rsum1 * c1 + ls1;
#pragma unroll
        for (int jo = 0; jo < 8; jo++) {
            o[jo][0] *= c0; o[jo][1] *= c0;
            o[jo][2] *= c1; o[jo][3] *= c1;
        }
        // O += P @ V
#pragma unroll
        for (int kk = 0; kk < 4; kk++)
#pragma unroll
        for (int jo = 0; jo < 8; jo++) {
            u32 b[2];
            b[0] = ld32(&Vs[buf][8*jo + g][kk*16     + 2*tg]);
            b[1] = ld32(&Vs[buf][8*jo + g][kk*16 + 8 + 2*tg]);
            mma16816(o[jo], pa[kk], b);
        }
        __syncthreads();
    }
    // finalize & write attention output [b*T+t, h*HS+s] bf16 (packed)
    float inv0 = 1.f / rsum0, inv1 = 1.f / rsum1;
    int b = bh >> 2, h = bh & 3;
#pragma unroll
    for (int jo = 0; jo < 8; jo++) {
        int sc = 8*jo + 2*tg;
        *reinterpret_cast<u32*>(&g_ao[(long)(b*T_ + r0)*DM + h*HS + sc]) =
            packbf(o[jo][0]*inv0, o[jo][1]*inv0);
        *reinterpret_cast<u32*>(&g_ao[(long)(b*T_ + r0 + 8)*DM + h*HS + sc]) =
            packbf(o[jo][2]*inv1, o[jo][3]*inv1);
    }
}

// ---------------- K4: out projection + bias + residual, double-buffered ----------------
__global__ __launch_bounds__(256) void out_kernel(const float* __restrict__ bo,
                                                  const float* __restrict__ resid,
                                                  float* __restrict__ out) {
    extern __shared__ __align__(16) bf16 dsm[];
    bf16 (*As)[LDA] = reinterpret_cast<bf16(*)[LDA]>(dsm);
    bf16 (*Bs)[LDA] = reinterpret_cast<bf16(*)[LDA]>(dsm + 2*128*LDA);
    int m0 = blockIdx.x * 128, n0 = blockIdx.y * 128;
    const bf16* A = g_ao;
    const bf16* W = g_Wt[4];
    int tid = threadIdx.x;
    int wid = tid >> 5, lane = tid & 31;
    int wm = wid & 3, wn = wid >> 2;
    int g = lane >> 2, tg = lane & 3;

    auto stage = [&](int buf, int k0) {
#pragma unroll
        for (int i = 0; i < 4; i++) {
            int cid = tid + 256*i;
            int row = cid >> 3, seg = cid & 7;
            cpasync16(&As[buf*128 + row][seg*8], A + (size_t)(m0 + row)*DM + k0 + seg*8);
            cpasync16(&Bs[buf*128 + row][seg*8], W + (size_t)(n0 + row)*DM + k0 + seg*8);
        }
        CP_COMMIT();
    };

    float acc[2][8][4] = {};
    stage(0, 0);
    for (int c = 0; c < DM/KCH; c++) {
        if (c + 1 < DM/KCH) { stage((c+1) & 1, (c+1)*KCH); CP_WAIT(1); }
        else                { CP_WAIT(0); }
        __syncthreads();
        int bo_ = (c & 1) * 128;
#pragma unroll
        for (int ks = 0; ks < KCH/16; ks++) {
            u32 a[2][4];
#pragma unroll
            for (int mt = 0; mt < 2; mt++) {
                int rb = bo_ + wm*32 + mt*16 + g;
                a[mt][0] = ld32(&As[rb  ][ks*16 + 2*tg]);
                a[mt][1] = ld32(&As[rb+8][ks*16 + 2*tg]);
                a[mt][2] = ld32(&As[rb  ][ks*16 + 8 + 2*tg]);
                a[mt][3] = ld32(&As[rb+8][ks*16 + 8 + 2*tg]);
            }
#pragma unroll
            for (int nt = 0; nt < 8; nt++) {
                int nb = bo_ + wn*64 + nt*8 + g;
                u32 b[2];
                b[0] = ld32(&Bs[nb][ks*16 + 2*tg]);
                b[1] = ld32(&Bs[nb][ks*16 + 8 + 2*tg]);
                mma16816(acc[0][nt], a[0], b);
                mma16816(acc[1][nt], a[1], b);
            }
        }
        __syncthreads();
    }
#pragma unroll
    for (int mt = 0; mt < 2; mt++)
#pragma unroll
    for (int nt = 0; nt < 8; nt++)
#pragma unroll
    for (int e = 0; e < 4; e++) {
        int rr = m0 + wm*32 + mt*16 + g + ((e >= 2) ? 8 : 0);
        int cc = n0 + wn*64 + nt*8 + 2*tg + (e & 1);
        out[(size_t)rr*DM + cc] = acc[mt][nt][e] + bo[cc] + resid[(size_t)rr*DM + cc];
    }
}

// ---------------- launch ----------------
extern "C" void kernel_launch(void* const* d_in, const int* in_sizes, int n_in,
                              void* d_out, int out_size) {
    const float* inputs  = (const float*)d_in[0];
    const float* pos_enc = (const float*)d_in[1];
    const float* gamma   = (const float*)d_in[2];
    const float* beta    = (const float*)d_in[3];
    const float* Wq      = (const float*)d_in[4];
    const float* bq      = (const float*)d_in[5];
    const float* Wk      = (const float*)d_in[6];
    const float* bk      = (const float*)d_in[7];
    const float* Wv      = (const float*)d_in[8];
    const float* bv      = (const float*)d_in[9];
    const float* Wp      = (const float*)d_in[10];
    const float* Wo      = (const float*)d_in[11];
    const float* bo      = (const float*)d_in[12];
    const float* pbu     = (const float*)d_in[13];
    const float* pbv     = (const float*)d_in[14];
    float* out = (float*)d_out;

    static bool attr_set = false;
    if (!attr_set) {
        cudaFuncSetAttribute(proj_kernel, cudaFuncAttributeMaxDynamicSharedMemorySize, GEMM_SMEM);
        cudaFuncSetAttribute(out_kernel,  cudaFuncAttributeMaxDynamicSharedMemorySize, GEMM_SMEM);
        attr_set = true;
    }

    ln_kernel<<<BT/8, 256>>>(inputs, gamma, beta);
    cvt_pe_kernel<<<(BT*DM + 1023)/1024, 1024>>>(pos_enc);
    wt_kernel<<<(5*DM*DM + 255)/256, 256>>>(Wq, Wk, Wv, Wp, Wo);
    proj_kernel<<<dim3(BT/128, DM/128, 4), 256, GEMM_SMEM>>>(bq, bk, bv, pbu, pbv);
    pos_kernel<<<dim3(T_/128, T_/128, BH), 256>>>();
    attn_kernel<<<dim3(T_/128, BH), 256>>>();
    out_kernel<<<dim3(BT/128, DM/128), 256, GEMM_SMEM>>>(bo, inputs, out);
}

// round 8
// speedup vs baseline: 1.0105x; 1.0105x over previous
#include <cuda_runtime.h>
#include <cuda_bf16.h>
#include <cstdint>

// Problem dims
#define B_  16
#define T_  1024
#define DM  256
#define H_  4
#define HS  64
#define BT  (B_*T_)    // 16384
#define BH  (B_*H_)    // 64

typedef unsigned int u32;
typedef __nv_bfloat16 bf16;

// ---------------- scratch (device globals: allocation-free rule) ----------------
__device__ __align__(256) bf16 g_x [BT*DM];          // LN output
__device__ __align__(256) bf16 g_pe[BT*DM];          // pos_enc bf16
__device__ __align__(256) bf16 g_Wt[5][DM*DM];       // transposed weights [n][k]: q,k,v,p,o
__device__ __align__(256) bf16 g_qu[BH*T_*HS];       // q + bq + pos_bias_u, [b,h,t,s]
__device__ __align__(256) bf16 g_qv[BH*T_*HS];       // q + bq + pos_bias_v
__device__ __align__(256) bf16 g_kk[BH*T_*HS];
__device__ __align__(256) bf16 g_pp[BH*T_*HS];       // pos projection
__device__ __align__(256) bf16 g_vt[BH*HS*T_];       // V transposed [b,h,s,t]
__device__ __align__(256) bf16 g_P [BH*(long)T_*T_]; // pre-shift pos scores (128 MB)
__device__ __align__(256) bf16 g_ao[BT*DM];          // attention output, [b*T+t, h*HS+s]

// ---------------- helpers ----------------
__device__ __forceinline__ u32 ld32(const bf16* p) {
    return *reinterpret_cast<const u32*>(p);
}
__device__ __forceinline__ u32 packbf(float lo, float hi) {
    __nv_bfloat162 v = __floats2bfloat162_rn(lo, hi);
    return *reinterpret_cast<u32*>(&v);
}
// mma.sync m16n8k16 row.col f32 += bf16*bf16
__device__ __forceinline__ void mma16816(float* c, const u32* a, const u32* b) {
    asm volatile(
        "mma.sync.aligned.m16n8k16.row.col.f32.bf16.bf16.f32 "
        "{%0,%1,%2,%3}, {%4,%5,%6,%7}, {%8,%9}, {%0,%1,%2,%3};\n"
        : "+f"(c[0]), "+f"(c[1]), "+f"(c[2]), "+f"(c[3])
        : "r"(a[0]), "r"(a[1]), "r"(a[2]), "r"(a[3]), "r"(b[0]), "r"(b[1]));
}
__device__ __forceinline__ u32 s2u(const void* p) {
    return (u32)__cvta_generic_to_shared(p);
}
// ldmatrix x4: per-lane address sa; lanes 0-7/8-15/16-23/24-31 address matrices 0..3
__device__ __forceinline__ void ldsm4(u32* r, u32 sa) {
    asm volatile("ldmatrix.sync.aligned.m8n8.x4.shared.b16 {%0,%1,%2,%3}, [%4];\n"
        : "=r"(r[0]), "=r"(r[1]), "=r"(r[2]), "=r"(r[3]) : "r"(sa));
}
__device__ __forceinline__ void cpasync16(void* smem, const void* gmem) {
    u32 sa = (u32)__cvta_generic_to_shared(smem);
    asm volatile("cp.async.cg.shared.global [%0], [%1], 16;\n" :: "r"(sa), "l"(gmem));
}
#define CP_COMMIT() asm volatile("cp.async.commit_group;\n")
#define CP_WAIT(n)  asm volatile("cp.async.wait_group %0;\n" :: "n"(n))

// A-matrix ldmatrix lane mapping: mats [m+0/k0, m+8/k0, m+0/k8, m+8/k8] -> a0..a3
#define AROW(lane) (((lane) & 7) + (((lane) >> 3) & 1) * 8)
#define ACOL(lane) ((((lane) >> 4) & 1) * 8)
// B-matrix ldmatrix lane mapping: mats [n/k0, n/k8, n+8/k0, n+8/k8] -> b(nt)={r0,r1}, b(nt+1)={r2,r3}
#define BROW(lane) (((lane) & 7) + (((lane) >> 4) & 1) * 8)
#define BCOL(lane) ((((lane) >> 3) & 1) * 8)

// ---------------- K0a: LayerNorm -> g_x (bf16) ----------------
__global__ void ln_kernel(const float* __restrict__ in,
                          const float* __restrict__ gamma,
                          const float* __restrict__ beta) {
    int row  = blockIdx.x * 8 + (threadIdx.x >> 5);
    int lane = threadIdx.x & 31;
    const float* r = in + (size_t)row * DM;
    float v[8];
    float s = 0.f;
#pragma unroll
    for (int i = 0; i < 8; i++) { v[i] = r[lane + 32*i]; s += v[i]; }
#pragma unroll
    for (int o = 16; o; o >>= 1) s += __shfl_xor_sync(0xffffffffu, s, o);
    float mu = s * (1.0f / DM);
    float vs = 0.f;
#pragma unroll
    for (int i = 0; i < 8; i++) { float d = v[i] - mu; vs += d * d; }
#pragma unroll
    for (int o = 16; o; o >>= 1) vs += __shfl_xor_sync(0xffffffffu, vs, o);
    float rstd = rsqrtf(vs * (1.0f / DM) + 1e-3f);
#pragma unroll
    for (int i = 0; i < 8; i++) {
        int c = lane + 32*i;
        g_x[(size_t)row*DM + c] =
            __float2bfloat16((v[i] - mu) * rstd * gamma[c] + beta[c]);
    }
}

// ---------------- K0b: pos_enc -> bf16 ----------------
__global__ void cvt_pe_kernel(const float* __restrict__ pe) {
    int i = blockIdx.x * blockDim.x + threadIdx.x;
    if (i < BT*DM) g_pe[i] = __float2bfloat16(pe[i]);
}

// ---------------- K0c: transpose+cvt the 5 weight matrices ----------------
__global__ void wt_kernel(const float* __restrict__ Wq, const float* __restrict__ Wk,
                          const float* __restrict__ Wv, const float* __restrict__ Wp,
                          const float* __restrict__ Wo) {
    int idx = blockIdx.x * blockDim.x + threadIdx.x;
    if (idx >= 5*DM*DM) return;
    int w = idx >> 16;
    int e = idx & 65535;
    int n = e >> 8, k = e & 255;
    const float* src = (w==0) ? Wq : (w==1) ? Wk : (w==2) ? Wv : (w==3) ? Wp : Wo;
    g_Wt[w][n*DM + k] = __float2bfloat16(src[k*DM + n]);
}

// ---------------- K1: projection GEMM (q/k/v/p), double-buffered + ldmatrix ----------------
// grid (BT/128, 256/128, 4), block 256 (8 warps, 4x2 warp grid, warp tile 32x64)
#define KCH 64
#define LDA 72
#define GEMM_SMEM (4 * 128 * LDA * 2)   // As[2]+Bs[2], 73728 bytes
__global__ __launch_bounds__(256) void proj_kernel(
    const float* __restrict__ bq, const float* __restrict__ bk,
    const float* __restrict__ bv, const float* __restrict__ pbu,
    const float* __restrict__ pbv) {
    extern __shared__ __align__(16) bf16 dsm[];
    bf16 (*As)[LDA] = reinterpret_cast<bf16(*)[LDA]>(dsm);                 // [2*128][LDA]
    bf16 (*Bs)[LDA] = reinterpret_cast<bf16(*)[LDA]>(dsm + 2*128*LDA);
    int which = blockIdx.z;
    int m0 = blockIdx.x * 128, n0 = blockIdx.y * 128;
    const bf16* A = (which == 3) ? g_pe : g_x;
    const bf16* W = g_Wt[which];
    int tid = threadIdx.x;
    int wid = tid >> 5, lane = tid & 31;
    int wm = wid & 3, wn = wid >> 2;
    int g = lane >> 2, tg = lane & 3;
    int arow = AROW(lane), acol = ACOL(lane);
    int brow = BROW(lane), bcol = BCOL(lane);

    auto stage = [&](int buf, int k0) {
#pragma unroll
        for (int i = 0; i < 4; i++) {
            int cid = tid + 256*i;
            int row = cid >> 3, seg = cid & 7;
            cpasync16(&As[buf*128 + row][seg*8], A + (size_t)(m0 + row)*DM + k0 + seg*8);
            cpasync16(&Bs[buf*128 + row][seg*8], W + (size_t)(n0 + row)*DM + k0 + seg*8);
        }
        CP_COMMIT();
    };

    float acc[2][8][4] = {};
    stage(0, 0);
    for (int c = 0; c < DM/KCH; c++) {
        if (c + 1 < DM/KCH) { stage((c+1) & 1, (c+1)*KCH); CP_WAIT(1); }
        else                { CP_WAIT(0); }
        __syncthreads();
        int bo_ = (c & 1) * 128;
#pragma unroll
        for (int ks = 0; ks < KCH/16; ks++) {
            u32 a[2][4];
#pragma unroll
            for (int mt = 0; mt < 2; mt++)
                ldsm4(a[mt], s2u(&As[bo_ + wm*32 + mt*16 + arow][ks*16 + acol]));
#pragma unroll
            for (int ntp = 0; ntp < 4; ntp++) {
                u32 r[4];
                ldsm4(r, s2u(&Bs[bo_ + wn*64 + ntp*16 + brow][ks*16 + bcol]));
                mma16816(acc[0][2*ntp],   a[0], &r[0]);
                mma16816(acc[0][2*ntp+1], a[0], &r[2]);
                mma16816(acc[1][2*ntp],   a[1], &r[0]);
                mma16816(acc[1][2*ntp+1], a[1], &r[2]);
            }
        }
        __syncthreads();
    }
#pragma unroll
    for (int mt = 0; mt < 2; mt++)
#pragma unroll
    for (int nt = 0; nt < 8; nt++)
#pragma unroll
    for (int e = 0; e < 4; e++) {
        int rr = m0 + wm*32 + mt*16 + g + ((e >= 2) ? 8 : 0);
        int cc = n0 + wn*64 + nt*8 + 2*tg + (e & 1);
        float val = acc[mt][nt][e];
        int b = rr >> 10, t = rr & (T_-1);
        int h = cc >> 6,  s = cc & (HS-1);
        long o = ((long)(b*H_ + h)*T_ + t)*HS + s;
        if (which == 0) {
            float q = val + bq[cc];
            g_qu[o] = __float2bfloat16(q + pbu[cc]);
            g_qv[o] = __float2bfloat16(q + pbv[cc]);
        } else if (which == 1) {
            g_kk[o] = __float2bfloat16(val + bk[cc]);
        } else if (which == 2) {
            g_vt[((long)(b*H_ + h)*HS + s)*T_ + t] = __float2bfloat16(val + bv[cc]);
        } else {
            g_pp[o] = __float2bfloat16(val);
        }
    }
}

// ---------------- K2: pre-shift pos scores P[bh] = qv @ pp^T, smem + ldmatrix ----------------
// grid (T/128, T/128, BH), block 256; K=64 single chunk
#define SPAD 8
__global__ __launch_bounds__(256) void pos_kernel() {
    __shared__ __align__(16) bf16 As[128][KCH + SPAD];
    __shared__ __align__(16) bf16 Bs[128][KCH + SPAD];
    int bh = blockIdx.z;
    int m0 = blockIdx.x * 128, n0 = blockIdx.y * 128;
    const bf16* A = g_qv + (long)bh * T_ * HS;
    const bf16* Bm = g_pp + (long)bh * T_ * HS;
    bf16* out = g_P + (long)bh * T_ * T_;
    int tid = threadIdx.x;
    int wid = tid >> 5, lane = tid & 31;
    int wm = wid & 3, wn = wid >> 2;
    int g = lane >> 2, tg = lane & 3;
    int arow = AROW(lane), acol = ACOL(lane);
    int brow = BROW(lane), bcol = BCOL(lane);

#pragma unroll
    for (int i = 0; i < 4; i++) {
        int cid = tid + 256*i;
        int row = cid >> 3, seg = cid & 7;
        cpasync16(&As[row][seg*8], A + (long)(m0 + row)*HS + seg*8);
        cpasync16(&Bs[row][seg*8], Bm + (long)(n0 + row)*HS + seg*8);
    }
    CP_COMMIT(); CP_WAIT(0);
    __syncthreads();

    float acc[2][8][4] = {};
#pragma unroll
    for (int ks = 0; ks < 4; ks++) {
        u32 a[2][4];
#pragma unroll
        for (int mt = 0; mt < 2; mt++)
            ldsm4(a[mt], s2u(&As[wm*32 + mt*16 + arow][ks*16 + acol]));
#pragma unroll
        for (int ntp = 0; ntp < 4; ntp++) {
            u32 r[4];
            ldsm4(r, s2u(&Bs[wn*64 + ntp*16 + brow][ks*16 + bcol]));
            mma16816(acc[0][2*ntp],   a[0], &r[0]);
            mma16816(acc[0][2*ntp+1], a[0], &r[2]);
            mma16816(acc[1][2*ntp],   a[1], &r[0]);
            mma16816(acc[1][2*ntp+1], a[1], &r[2]);
        }
    }
    // packed u32 stores (pairs of consecutive cols)
#pragma unroll
    for (int mt = 0; mt < 2; mt++)
#pragma unroll
    for (int nt = 0; nt < 8; nt++) {
        int rr = m0 + wm*32 + mt*16 + g;
        int cc = n0 + wn*64 + nt*8 + 2*tg;
        *reinterpret_cast<u32*>(out + (long)rr*T_ + cc)     = packbf(acc[mt][nt][0], acc[mt][nt][1]);
        *reinterpret_cast<u32*>(out + (long)(rr+8)*T_ + cc) = packbf(acc[mt][nt][2], acc[mt][nt][3]);
    }
}

// ---------------- K3: flash attention, 128-row q-tile, K/V smem + ldmatrix ----------------
// grid (T/128, BH), block 256 (8 warps x 16 query rows)
// shift(P)[m,n] = (n==m+1) ? 0 : P_flat[m*T + (T-1-m) + n - (n>m)]
__global__ __launch_bounds__(256) void attn_kernel() {
    __shared__ __align__(16) bf16 Ks[2][64][72];
    __shared__ __align__(16) bf16 Vs[2][64][72];
    int bh = blockIdx.y;
    int m0 = blockIdx.x * 128;
    int tid = threadIdx.x;
    int wid = tid >> 5, lane = tid & 31;
    int g = lane >> 2, tg = lane & 3;
    int brow = BROW(lane), bcol = BCOL(lane);
    const bf16* Qu = g_qu + (long)bh * T_ * HS;
    const bf16* K  = g_kk + (long)bh * T_ * HS;
    const bf16* Vt = g_vt + (long)bh * HS * T_;
    const bf16* Pm = g_P  + (long)bh * T_ * T_;
    int r0 = m0 + wid*16 + g;

    // persistent QU fragments
    u32 aq[4][4];
#pragma unroll
    for (int kk = 0; kk < 4; kk++) {
        aq[kk][0] = ld32(Qu + (long) r0   *HS + kk*16     + 2*tg);
        aq[kk][1] = ld32(Qu + (long)(r0+8)*HS + kk*16     + 2*tg);
        aq[kk][2] = ld32(Qu + (long) r0   *HS + kk*16 + 8 + 2*tg);
        aq[kk][3] = ld32(Qu + (long)(r0+8)*HS + kk*16 + 8 + 2*tg);
    }

    // stage(buf, n0): K rows [n0..n0+64) x 64 cols; Vt rows (s) 0..64 x cols [n0..n0+64)
    // 64 rows x 8 seg16 = 512 cp16 per matrix; 256 threads -> 2 iterations
    auto stage = [&](int buf, int n0) {
#pragma unroll
        for (int i = 0; i < 2; i++) {
            int cid = tid + 256*i;
            int row = cid >> 3, seg = cid & 7;   // row 0..63, seg 0..7 (16B = 8 bf16)
            cpasync16(&Ks[buf][row][seg*8], K  + (long)(n0 + row)*HS + seg*8);
            cpasync16(&Vs[buf][row][seg*8], Vt + (long)row*T_ + n0 + seg*8);
        }
        CP_COMMIT();
    };

    float mrow0 = -1e30f, mrow1 = -1e30f;
    float rsum0 = 0.f, rsum1 = 0.f;
    float o[8][4] = {};

    stage(0, 0);
    for (int it = 0; it < T_/64; it++) {
        int n0 = it * 64;
        int buf = it & 1;
        if (it + 1 < T_/64) { stage(buf ^ 1, n0 + 64); CP_WAIT(1); }
        else                { CP_WAIT(0); }
        __syncthreads();

        // S = QU @ K^T
        float s[8][4] = {};
#pragma unroll
        for (int kk = 0; kk < 4; kk++)
#pragma unroll
        for (int jp = 0; jp < 4; jp++) {
            u32 r[4];
            ldsm4(r, s2u(&Ks[buf][jp*16 + brow][kk*16 + bcol]));
            mma16816(s[2*jp],   aq[kk], &r[0]);
            mma16816(s[2*jp+1], aq[kk], &r[2]);
        }
        // add shifted pos scores, scale
#pragma unroll
        for (int j = 0; j < 8; j++)
#pragma unroll
        for (int e = 0; e < 4; e++) {
            int rr = r0 + ((e >= 2) ? 8 : 0);
            int nn = n0 + 8*j + 2*tg + (e & 1);
            float pos = 0.f;
            if (nn != rr + 1) {
                long idx = (long)rr*T_ + (T_ - 1 - rr) + nn - (nn > rr ? 1 : 0);
                pos = __bfloat162float(Pm[idx]);
            }
            s[j][e] = (s[j][e] + pos) * 0.125f;
        }
        // online softmax
        float lm0 = -1e30f, lm1 = -1e30f;
#pragma unroll
        for (int j = 0; j < 8; j++) {
            lm0 = fmaxf(lm0, fmaxf(s[j][0], s[j][1]));
            lm1 = fmaxf(lm1, fmaxf(s[j][2], s[j][3]));
        }
        lm0 = fmaxf(lm0, __shfl_xor_sync(0xffffffffu, lm0, 1));
        lm0 = fmaxf(lm0, __shfl_xor_sync(0xffffffffu, lm0, 2));
        lm1 = fmaxf(lm1, __shfl_xor_sync(0xffffffffu, lm1, 1));
        lm1 = fmaxf(lm1, __shfl_xor_sync(0xffffffffu, lm1, 2));
        float nm0 = fmaxf(mrow0, lm0), nm1 = fmaxf(mrow1, lm1);
        float c0 = __expf(mrow0 - nm0), c1 = __expf(mrow1 - nm1);
        mrow0 = nm0; mrow1 = nm1;

        u32 pa[4][4];
        float ls0 = 0.f, ls1 = 0.f;
#pragma unroll
        for (int j = 0; j < 8; j++) {
            float p0 = __expf(s[j][0] - nm0);
            float p1 = __expf(s[j][1] - nm0);
            float p2 = __expf(s[j][2] - nm1);
            float p3 = __expf(s[j][3] - nm1);
            ls0 += p0 + p1; ls1 += p2 + p3;
            pa[j >> 1][(j & 1) ? 2 : 0] = packbf(p0, p1);
            pa[j >> 1][(j & 1) ? 3 : 1] = packbf(p2, p3);
        }
        ls0 += __shfl_xor_sync(0xffffffffu, ls0, 1);
        ls0 += __shfl_xor_sync(0xffffffffu, ls0, 2);
        ls1 += __shfl_xor_sync(0xffffffffu, ls1, 1);
        ls1 += __shfl_xor_sync(0xffffffffu, ls1, 2);
        rsum0 = rsum0 * c0 + ls0;
        rsum1 = rsum1 * c1 + ls1;
#pragma unroll
        for (int jo = 0; jo < 8; jo++) {
            o[jo][0] *= c0; o[jo][1] *= c0;
            o[jo][2] *= c1; o[jo][3] *= c1;
        }
        // O += P @ V
#pragma unroll
        for (int kk = 0; kk < 4; kk++)
#pragma unroll
        for (int jp = 0; jp < 4; jp++) {
            u32 r[4];
            ldsm4(r, s2u(&Vs[buf][jp*16 + brow][kk*16 + bcol]));
            mma16816(o[2*jp],   pa[kk], &r[0]);
            mma16816(o[2*jp+1], pa[kk], &r[2]);
        }
        __syncthreads();
    }
    // finalize & write attention output [b*T+t, h*HS+s] bf16 (packed)
    float inv0 = 1.f / rsum0, inv1 = 1.f / rsum1;
    int b = bh >> 2, h = bh & 3;
#pragma unroll
    for (int jo = 0; jo < 8; jo++) {
        int sc = 8*jo + 2*tg;
        *reinterpret_cast<u32*>(&g_ao[(long)(b*T_ + r0)*DM + h*HS + sc]) =
            packbf(o[jo][0]*inv0, o[jo][1]*inv0);
        *reinterpret_cast<u32*>(&g_ao[(long)(b*T_ + r0 + 8)*DM + h*HS + sc]) =
            packbf(o[jo][2]*inv1, o[jo][3]*inv1);
    }
}

// ---------------- K4: out projection + bias + residual, double-buffered + ldmatrix ----------------
__global__ __launch_bounds__(256) void out_kernel(const float* __restrict__ bo,
                                                  const float* __restrict__ resid,
                                                  float* __restrict__ out) {
    extern __shared__ __align__(16) bf16 dsm[];
    bf16 (*As)[LDA] = reinterpret_cast<bf16(*)[LDA]>(dsm);
    bf16 (*Bs)[LDA] = reinterpret_cast<bf16(*)[LDA]>(dsm + 2*128*LDA);
    int m0 = blockIdx.x * 128, n0 = blockIdx.y * 128;
    const bf16* A = g_ao;
    const bf16* W = g_Wt[4];
    int tid = threadIdx.x;
    int wid = tid >> 5, lane = tid & 31;
    int wm = wid & 3, wn = wid >> 2;
    int g = lane >> 2, tg = lane & 3;
    int arow = AROW(lane), acol = ACOL(lane);
    int brow = BROW(lane), bcol = BCOL(lane);

    auto stage = [&](int buf, int k0) {
#pragma unroll
        for (int i = 0; i < 4; i++) {
            int cid = tid + 256*i;
            int row = cid >> 3, seg = cid & 7;
            cpasync16(&As[buf*128 + row][seg*8], A + (size_t)(m0 + row)*DM + k0 + seg*8);
            cpasync16(&Bs[buf*128 + row][seg*8], W + (size_t)(n0 + row)*DM + k0 + seg*8);
        }
        CP_COMMIT();
    };

    float acc[2][8][4] = {};
    stage(0, 0);
    for (int c = 0; c < DM/KCH; c++) {
        if (c + 1 < DM/KCH) { stage((c+1) & 1, (c+1)*KCH); CP_WAIT(1); }
        else                { CP_WAIT(0); }
        __syncthreads();
        int bo_ = (c & 1) * 128;
#pragma unroll
        for (int ks = 0; ks < KCH/16; ks++) {
            u32 a[2][4];
#pragma unroll
            for (int mt = 0; mt < 2; mt++)
                ldsm4(a[mt], s2u(&As[bo_ + wm*32 + mt*16 + arow][ks*16 + acol]));
#pragma unroll
            for (int ntp = 0; ntp < 4; ntp++) {
                u32 r[4];
                ldsm4(r, s2u(&Bs[bo_ + wn*64 + ntp*16 + brow][ks*16 + bcol]));
                mma16816(acc[0][2*ntp],   a[0], &r[0]);
                mma16816(acc[0][2*ntp+1], a[0], &r[2]);
                mma16816(acc[1][2*ntp],   a[1], &r[0]);
                mma16816(acc[1][2*ntp+1], a[1], &r[2]);
            }
        }
        __syncthreads();
    }
#pragma unroll
    for (int mt = 0; mt < 2; mt++)
#pragma unroll
    for (int nt = 0; nt < 8; nt++)
#pragma unroll
    for (int e = 0; e < 4; e++) {
        int rr = m0 + wm*32 + mt*16 + g + ((e >= 2) ? 8 : 0);
        int cc = n0 + wn*64 + nt*8 + 2*tg + (e & 1);
        out[(size_t)rr*DM + cc] = acc[mt][nt][e] + bo[cc] + resid[(size_t)rr*DM + cc];
    }
}

// ---------------- launch ----------------
extern "C" void kernel_launch(void* const* d_in, const int* in_sizes, int n_in,
                              void* d_out, int out_size) {
    const float* inputs  = (const float*)d_in[0];
    const float* pos_enc = (const float*)d_in[1];
    const float* gamma   = (const float*)d_in[2];
    const float* beta    = (const float*)d_in[3];
    const float* Wq      = (const float*)d_in[4];
    const float* bq      = (const float*)d_in[5];
    const float* Wk      = (const float*)d_in[6];
    const float* bk      = (const float*)d_in[7];
    const float* Wv      = (const float*)d_in[8];
    const float* bv      = (const float*)d_in[9];
    const float* Wp      = (const float*)d_in[10];
    const float* Wo      = (const float*)d_in[11];
    const float* bo      = (const float*)d_in[12];
    const float* pbu     = (const float*)d_in[13];
    const float* pbv     = (const float*)d_in[14];
    float* out = (float*)d_out;

    static bool attr_set = false;
    if (!attr_set) {
        cudaFuncSetAttribute(proj_kernel, cudaFuncAttributeMaxDynamicSharedMemorySize, GEMM_SMEM);
        cudaFuncSetAttribute(out_kernel,  cudaFuncAttributeMaxDynamicSharedMemorySize, GEMM_SMEM);
        attr_set = true;
    }

    ln_kernel<<<BT/8, 256>>>(inputs, gamma, beta);
    cvt_pe_kernel<<<(BT*DM + 1023)/1024, 1024>>>(pos_enc);
    wt_kernel<<<(5*DM*DM + 255)/256, 256>>>(Wq, Wk, Wv, Wp, Wo);
    proj_kernel<<<dim3(BT/128, DM/128, 4), 256, GEMM_SMEM>>>(bq, bk, bv, pbu, pbv);
    pos_kernel<<<dim3(T_/128, T_/128, BH), 256>>>();
    attn_kernel<<<dim3(T_/128, BH), 256>>>();
    out_kernel<<<dim3(BT/128, DM/128), 256, GEMM_SMEM>>>(bo, inputs, out);
}

// round 9
// speedup vs baseline: 1.1087x; 1.0971x over previous
#include <cuda_runtime.h>
#include <cuda_bf16.h>
#include <cstdint>

// Problem dims
#define B_  16
#define T_  1024
#define DM  256
#define H_  4
#define HS  64
#define BT  (B_*T_)    // 16384
#define BH  (B_*H_)    // 64

typedef unsigned int u32;
typedef __nv_bfloat16 bf16;

// ---------------- scratch (device globals: allocation-free rule) ----------------
__device__ __align__(256) bf16 g_x [BT*DM];          // LN output
__device__ __align__(256) bf16 g_pe[BT*DM];          // pos_enc bf16
__device__ __align__(256) bf16 g_Wt[5][DM*DM];       // transposed weights [n][k]: q,k,v,p,o
__device__ __align__(256) bf16 g_qu[BH*T_*HS];       // q + bq + pos_bias_u, [b,h,t,s]
__device__ __align__(256) bf16 g_qv[BH*T_*HS];       // q + bq + pos_bias_v
__device__ __align__(256) bf16 g_kk[BH*T_*HS];
__device__ __align__(256) bf16 g_pp[BH*T_*HS];       // pos projection
__device__ __align__(256) bf16 g_vv[BH*T_*HS];       // V, [b,h,t,s] (transposed in attn via ldmatrix.trans)
__device__ __align__(256) bf16 g_P [BH*(long)T_*T_]; // pre-shift pos scores (128 MB)
__device__ __align__(256) bf16 g_ao[BT*DM];          // attention output, [b*T+t, h*HS+s]

// ---------------- helpers ----------------
__device__ __forceinline__ u32 ld32(const bf16* p) {
    return *reinterpret_cast<const u32*>(p);
}
__device__ __forceinline__ u32 packbf(float lo, float hi) {
    __nv_bfloat162 v = __floats2bfloat162_rn(lo, hi);
    return *reinterpret_cast<u32*>(&v);
}
// mma.sync m16n8k16 row.col f32 += bf16*bf16
__device__ __forceinline__ void mma16816(float* c, const u32* a, const u32* b) {
    asm volatile(
        "mma.sync.aligned.m16n8k16.row.col.f32.bf16.bf16.f32 "
        "{%0,%1,%2,%3}, {%4,%5,%6,%7}, {%8,%9}, {%0,%1,%2,%3};\n"
        : "+f"(c[0]), "+f"(c[1]), "+f"(c[2]), "+f"(c[3])
        : "r"(a[0]), "r"(a[1]), "r"(a[2]), "r"(a[3]), "r"(b[0]), "r"(b[1]));
}
__device__ __forceinline__ u32 s2u(const void* p) {
    return (u32)__cvta_generic_to_shared(p);
}
// ldmatrix x4
__device__ __forceinline__ void ldsm4(u32* r, u32 sa) {
    asm volatile("ldmatrix.sync.aligned.m8n8.x4.shared.b16 {%0,%1,%2,%3}, [%4];\n"
        : "=r"(r[0]), "=r"(r[1]), "=r"(r[2]), "=r"(r[3]) : "r"(sa));
}
// ldmatrix x4 transposed (b16)
__device__ __forceinline__ void ldsm4t(u32* r, u32 sa) {
    asm volatile("ldmatrix.sync.aligned.m8n8.x4.trans.shared.b16 {%0,%1,%2,%3}, [%4];\n"
        : "=r"(r[0]), "=r"(r[1]), "=r"(r[2]), "=r"(r[3]) : "r"(sa));
}
__device__ __forceinline__ void cpasync16(void* smem, const void* gmem) {
    u32 sa = (u32)__cvta_generic_to_shared(smem);
    asm volatile("cp.async.cg.shared.global [%0], [%1], 16;\n" :: "r"(sa), "l"(gmem));
}
#define CP_COMMIT() asm volatile("cp.async.commit_group;\n")
#define CP_WAIT(n)  asm volatile("cp.async.wait_group %0;\n" :: "n"(n))

// A-matrix ldmatrix lane mapping: mats [m+0/k0, m+8/k0, m+0/k8, m+8/k8] -> a0..a3
#define AROW(lane) (((lane) & 7) + (((lane) >> 3) & 1) * 8)
#define ACOL(lane) ((((lane) >> 4) & 1) * 8)
// B-matrix ldmatrix lane mapping: mats [n/k0, n/k8, n+8/k0, n+8/k8] -> b(nt)={r0,r1}, b(nt+1)={r2,r3}
#define BROW(lane) (((lane) & 7) + (((lane) >> 4) & 1) * 8)
#define BCOL(lane) ((((lane) >> 3) & 1) * 8)
// trans-B ([k][n] stored, want [n][k] frags): mats [k0/n0, k8/n0, k0/n8, k8/n8]
#define TROW(lane) (((lane) & 7) + (((lane) >> 3) & 1) * 8)
#define TCOL(lane) ((((lane) >> 4) & 1) * 8)

// ---------------- K0a: LayerNorm -> g_x (bf16) ----------------
__global__ void ln_kernel(const float* __restrict__ in,
                          const float* __restrict__ gamma,
                          const float* __restrict__ beta) {
    int row  = blockIdx.x * 8 + (threadIdx.x >> 5);
    int lane = threadIdx.x & 31;
    const float* r = in + (size_t)row * DM;
    float v[8];
    float s = 0.f;
#pragma unroll
    for (int i = 0; i < 8; i++) { v[i] = r[lane + 32*i]; s += v[i]; }
#pragma unroll
    for (int o = 16; o; o >>= 1) s += __shfl_xor_sync(0xffffffffu, s, o);
    float mu = s * (1.0f / DM);
    float vs = 0.f;
#pragma unroll
    for (int i = 0; i < 8; i++) { float d = v[i] - mu; vs += d * d; }
#pragma unroll
    for (int o = 16; o; o >>= 1) vs += __shfl_xor_sync(0xffffffffu, vs, o);
    float rstd = rsqrtf(vs * (1.0f / DM) + 1e-3f);
#pragma unroll
    for (int i = 0; i < 8; i++) {
        int c = lane + 32*i;
        g_x[(size_t)row*DM + c] =
            __float2bfloat16((v[i] - mu) * rstd * gamma[c] + beta[c]);
    }
}

// ---------------- K0b: pos_enc -> bf16 ----------------
__global__ void cvt_pe_kernel(const float* __restrict__ pe) {
    int i = blockIdx.x * blockDim.x + threadIdx.x;
    if (i < BT*DM) g_pe[i] = __float2bfloat16(pe[i]);
}

// ---------------- K0c: transpose+cvt the 5 weight matrices ----------------
__global__ void wt_kernel(const float* __restrict__ Wq, const float* __restrict__ Wk,
                          const float* __restrict__ Wv, const float* __restrict__ Wp,
                          const float* __restrict__ Wo) {
    int idx = blockIdx.x * blockDim.x + threadIdx.x;
    if (idx >= 5*DM*DM) return;
    int w = idx >> 16;
    int e = idx & 65535;
    int n = e >> 8, k = e & 255;
    const float* src = (w==0) ? Wq : (w==1) ? Wk : (w==2) ? Wv : (w==3) ? Wp : Wo;
    g_Wt[w][n*DM + k] = __float2bfloat16(src[k*DM + n]);
}

// ---------------- K1: projection GEMM (q/k/v/p), double-buffered + ldmatrix ----------------
// grid (BT/128, 256/128, 4), block 256 (8 warps, 4x2 warp grid, warp tile 32x64)
#define KCH 64
#define LDA 72
#define GEMM_SMEM (4 * 128 * LDA * 2)   // As[2]+Bs[2], 73728 bytes
__global__ __launch_bounds__(256) void proj_kernel(
    const float* __restrict__ bq, const float* __restrict__ bk,
    const float* __restrict__ bv, const float* __restrict__ pbu,
    const float* __restrict__ pbv) {
    extern __shared__ __align__(16) bf16 dsm[];
    bf16 (*As)[LDA] = reinterpret_cast<bf16(*)[LDA]>(dsm);                 // [2*128][LDA]
    bf16 (*Bs)[LDA] = reinterpret_cast<bf16(*)[LDA]>(dsm + 2*128*LDA);
    int which = blockIdx.z;
    int m0 = blockIdx.x * 128, n0 = blockIdx.y * 128;
    const bf16* A = (which == 3) ? g_pe : g_x;
    const bf16* W = g_Wt[which];
    int tid = threadIdx.x;
    int wid = tid >> 5, lane = tid & 31;
    int wm = wid & 3, wn = wid >> 2;
    int g = lane >> 2, tg = lane & 3;
    int arow = AROW(lane), acol = ACOL(lane);
    int brow = BROW(lane), bcol = BCOL(lane);

    auto stage = [&](int buf, int k0) {
#pragma unroll
        for (int i = 0; i < 4; i++) {
            int cid = tid + 256*i;
            int row = cid >> 3, seg = cid & 7;
            cpasync16(&As[buf*128 + row][seg*8], A + (size_t)(m0 + row)*DM + k0 + seg*8);
            cpasync16(&Bs[buf*128 + row][seg*8], W + (size_t)(n0 + row)*DM + k0 + seg*8);
        }
        CP_COMMIT();
    };

    float acc[2][8][4] = {};
    stage(0, 0);
    for (int c = 0; c < DM/KCH; c++) {
        if (c + 1 < DM/KCH) { stage((c+1) & 1, (c+1)*KCH); CP_WAIT(1); }
        else                { CP_WAIT(0); }
        __syncthreads();
        int bo_ = (c & 1) * 128;
#pragma unroll
        for (int ks = 0; ks < KCH/16; ks++) {
            u32 a[2][4];
#pragma unroll
            for (int mt = 0; mt < 2; mt++)
                ldsm4(a[mt], s2u(&As[bo_ + wm*32 + mt*16 + arow][ks*16 + acol]));
#pragma unroll
            for (int ntp = 0; ntp < 4; ntp++) {
                u32 r[4];
                ldsm4(r, s2u(&Bs[bo_ + wn*64 + ntp*16 + brow][ks*16 + bcol]));
                mma16816(acc[0][2*ntp],   a[0], &r[0]);
                mma16816(acc[0][2*ntp+1], a[0], &r[2]);
                mma16816(acc[1][2*ntp],   a[1], &r[0]);
                mma16816(acc[1][2*ntp+1], a[1], &r[2]);
            }
        }
        __syncthreads();
    }
    // ---- packed u32 epilogue (no sub-sector scatter) ----
#pragma unroll
    for (int mt = 0; mt < 2; mt++)
#pragma unroll
    for (int nt = 0; nt < 8; nt++)
#pragma unroll
    for (int half = 0; half < 2; half++) {
        int rr = m0 + wm*32 + mt*16 + g + half*8;
        int cc = n0 + wn*64 + nt*8 + 2*tg;          // cc, cc+1 both in same head
        float v0 = acc[mt][nt][2*half], v1 = acc[mt][nt][2*half+1];
        int b = rr >> 10, t = rr & (T_-1);
        int h = cc >> 6,  s = cc & (HS-1);
        long o = ((long)(b*H_ + h)*T_ + t)*HS + s;
        if (which == 0) {
            float q0 = v0 + bq[cc], q1 = v1 + bq[cc+1];
            *reinterpret_cast<u32*>(&g_qu[o]) = packbf(q0 + pbu[cc], q1 + pbu[cc+1]);
            *reinterpret_cast<u32*>(&g_qv[o]) = packbf(q0 + pbv[cc], q1 + pbv[cc+1]);
        } else if (which == 1) {
            *reinterpret_cast<u32*>(&g_kk[o]) = packbf(v0 + bk[cc], v1 + bk[cc+1]);
        } else if (which == 2) {
            *reinterpret_cast<u32*>(&g_vv[o]) = packbf(v0 + bv[cc], v1 + bv[cc+1]);
        } else {
            *reinterpret_cast<u32*>(&g_pp[o]) = packbf(v0, v1);
        }
    }
}

// ---------------- K2: pre-shift pos scores P[bh] = qv @ pp^T, smem + ldmatrix ----------------
// grid (T/128, T/128, BH), block 256; K=64 single chunk
#define SPAD 8
__global__ __launch_bounds__(256) void pos_kernel() {
    __shared__ __align__(16) bf16 As[128][KCH + SPAD];
    __shared__ __align__(16) bf16 Bs[128][KCH + SPAD];
    int bh = blockIdx.z;
    int m0 = blockIdx.x * 128, n0 = blockIdx.y * 128;
    const bf16* A = g_qv + (long)bh * T_ * HS;
    const bf16* Bm = g_pp + (long)bh * T_ * HS;
    bf16* out = g_P + (long)bh * T_ * T_;
    int tid = threadIdx.x;
    int wid = tid >> 5, lane = tid & 31;
    int wm = wid & 3, wn = wid >> 2;
    int g = lane >> 2, tg = lane & 3;
    int arow = AROW(lane), acol = ACOL(lane);
    int brow = BROW(lane), bcol = BCOL(lane);

#pragma unroll
    for (int i = 0; i < 4; i++) {
        int cid = tid + 256*i;
        int row = cid >> 3, seg = cid & 7;
        cpasync16(&As[row][seg*8], A + (long)(m0 + row)*HS + seg*8);
        cpasync16(&Bs[row][seg*8], Bm + (long)(n0 + row)*HS + seg*8);
    }
    CP_COMMIT(); CP_WAIT(0);
    __syncthreads();

    float acc[2][8][4] = {};
#pragma unroll
    for (int ks = 0; ks < 4; ks++) {
        u32 a[2][4];
#pragma unroll
        for (int mt = 0; mt < 2; mt++)
            ldsm4(a[mt], s2u(&As[wm*32 + mt*16 + arow][ks*16 + acol]));
#pragma unroll
        for (int ntp = 0; ntp < 4; ntp++) {
            u32 r[4];
            ldsm4(r, s2u(&Bs[wn*64 + ntp*16 + brow][ks*16 + bcol]));
            mma16816(acc[0][2*ntp],   a[0], &r[0]);
            mma16816(acc[0][2*ntp+1], a[0], &r[2]);
            mma16816(acc[1][2*ntp],   a[1], &r[0]);
            mma16816(acc[1][2*ntp+1], a[1], &r[2]);
        }
    }
    // packed u32 stores (pairs of consecutive cols)
#pragma unroll
    for (int mt = 0; mt < 2; mt++)
#pragma unroll
    for (int nt = 0; nt < 8; nt++) {
        int rr = m0 + wm*32 + mt*16 + g;
        int cc = n0 + wn*64 + nt*8 + 2*tg;
        *reinterpret_cast<u32*>(out + (long)rr*T_ + cc)     = packbf(acc[mt][nt][0], acc[mt][nt][1]);
        *reinterpret_cast<u32*>(out + (long)(rr+8)*T_ + cc) = packbf(acc[mt][nt][2], acc[mt][nt][3]);
    }
}

// ---------------- K3: flash attention, 128-row q-tile, K/V smem + ldmatrix ----------------
// grid (T/128, BH), block 256 (8 warps x 16 query rows)
// shift(P)[m,n] = (n==m+1) ? 0 : P_flat[m*T + (T-1-m) + n - (n>m)]
__global__ __launch_bounds__(256) void attn_kernel() {
    __shared__ __align__(16) bf16 Ks[2][64][72];
    __shared__ __align__(16) bf16 Vs[2][64][72];
    int bh = blockIdx.y;
    int m0 = blockIdx.x * 128;
    int tid = threadIdx.x;
    int wid = tid >> 5, lane = tid & 31;
    int g = lane >> 2, tg = lane & 3;
    int brow = BROW(lane), bcol = BCOL(lane);
    int trow = TROW(lane), tcol = TCOL(lane);
    const bf16* Qu = g_qu + (long)bh * T_ * HS;
    const bf16* K  = g_kk + (long)bh * T_ * HS;
    const bf16* V  = g_vv + (long)bh * T_ * HS;
    const bf16* Pm = g_P  + (long)bh * T_ * T_;
    int r0 = m0 + wid*16 + g;

    // persistent QU fragments
    u32 aq[4][4];
#pragma unroll
    for (int kk = 0; kk < 4; kk++) {
        aq[kk][0] = ld32(Qu + (long) r0   *HS + kk*16     + 2*tg);
        aq[kk][1] = ld32(Qu + (long)(r0+8)*HS + kk*16     + 2*tg);
        aq[kk][2] = ld32(Qu + (long) r0   *HS + kk*16 + 8 + 2*tg);
        aq[kk][3] = ld32(Qu + (long)(r0+8)*HS + kk*16 + 8 + 2*tg);
    }

    // stage(buf, n0): K and V rows [n0..n0+64) x 64 cols, identical layout
    auto stage = [&](int buf, int n0) {
#pragma unroll
        for (int i = 0; i < 2; i++) {
            int cid = tid + 256*i;
            int row = cid >> 3, seg = cid & 7;   // row 0..63, seg 0..7 (16B = 8 bf16)
            cpasync16(&Ks[buf][row][seg*8], K + (long)(n0 + row)*HS + seg*8);
            cpasync16(&Vs[buf][row][seg*8], V + (long)(n0 + row)*HS + seg*8);
        }
        CP_COMMIT();
    };

    float mrow0 = -1e30f, mrow1 = -1e30f;
    float rsum0 = 0.f, rsum1 = 0.f;
    float o[8][4] = {};

    stage(0, 0);
    for (int it = 0; it < T_/64; it++) {
        int n0 = it * 64;
        int buf = it & 1;
        if (it + 1 < T_/64) { stage(buf ^ 1, n0 + 64); CP_WAIT(1); }
        else                { CP_WAIT(0); }
        __syncthreads();

        // S = QU @ K^T
        float s[8][4] = {};
#pragma unroll
        for (int kk = 0; kk < 4; kk++)
#pragma unroll
        for (int jp = 0; jp < 4; jp++) {
            u32 r[4];
            ldsm4(r, s2u(&Ks[buf][jp*16 + brow][kk*16 + bcol]));
            mma16816(s[2*jp],   aq[kk], &r[0]);
            mma16816(s[2*jp+1], aq[kk], &r[2]);
        }
        // add shifted pos scores, scale
#pragma unroll
        for (int j = 0; j < 8; j++)
#pragma unroll
        for (int e = 0; e < 4; e++) {
            int rr = r0 + ((e >= 2) ? 8 : 0);
            int nn = n0 + 8*j + 2*tg + (e & 1);
            float pos = 0.f;
            if (nn != rr + 1) {
                long idx = (long)rr*T_ + (T_ - 1 - rr) + nn - (nn > rr ? 1 : 0);
                pos = __bfloat162float(Pm[idx]);
            }
            s[j][e] = (s[j][e] + pos) * 0.125f;
        }
        // online softmax
        float lm0 = -1e30f, lm1 = -1e30f;
#pragma unroll
        for (int j = 0; j < 8; j++) {
            lm0 = fmaxf(lm0, fmaxf(s[j][0], s[j][1]));
            lm1 = fmaxf(lm1, fmaxf(s[j][2], s[j][3]));
        }
        lm0 = fmaxf(lm0, __shfl_xor_sync(0xffffffffu, lm0, 1));
        lm0 = fmaxf(lm0, __shfl_xor_sync(0xffffffffu, lm0, 2));
        lm1 = fmaxf(lm1, __shfl_xor_sync(0xffffffffu, lm1, 1));
        lm1 = fmaxf(lm1, __shfl_xor_sync(0xffffffffu, lm1, 2));
        float nm0 = fmaxf(mrow0, lm0), nm1 = fmaxf(mrow1, lm1);
        float c0 = __expf(mrow0 - nm0), c1 = __expf(mrow1 - nm1);
        mrow0 = nm0; mrow1 = nm1;

        u32 pa[4][4];
        float ls0 = 0.f, ls1 = 0.f;
#pragma unroll
        for (int j = 0; j < 8; j++) {
            float p0 = __expf(s[j][0] - nm0);
            float p1 = __expf(s[j][1] - nm0);
            float p2 = __expf(s[j][2] - nm1);
            float p3 = __expf(s[j][3] - nm1);
            ls0 += p0 + p1; ls1 += p2 + p3;
            pa[j >> 1][(j & 1) ? 2 : 0] = packbf(p0, p1);
            pa[j >> 1][(j & 1) ? 3 : 1] = packbf(p2, p3);
        }
        ls0 += __shfl_xor_sync(0xffffffffu, ls0, 1);
        ls0 += __shfl_xor_sync(0xffffffffu, ls0, 2);
        ls1 += __shfl_xor_sync(0xffffffffu, ls1, 1);
        ls1 += __shfl_xor_sync(0xffffffffu, ls1, 2);
        rsum0 = rsum0 * c0 + ls0;
        rsum1 = rsum1 * c1 + ls1;
#pragma unroll
        for (int jo = 0; jo < 8; jo++) {
            o[jo][0] *= c0; o[jo][1] *= c0;
            o[jo][2] *= c1; o[jo][3] *= c1;
        }
        // O += P @ V  (B-frags via ldmatrix.trans from [t][s] tile)
#pragma unroll
        for (int kk = 0; kk < 4; kk++)
#pragma unroll
        for (int jp = 0; jp < 4; jp++) {
            u32 r[4];
            ldsm4t(r, s2u(&Vs[buf][kk*16 + trow][jp*16 + tcol]));
            mma16816(o[2*jp],   pa[kk], &r[0]);
            mma16816(o[2*jp+1], pa[kk], &r[2]);
        }
        __syncthreads();
    }
    // finalize & write attention output [b*T+t, h*HS+s] bf16 (packed)
    float inv0 = 1.f / rsum0, inv1 = 1.f / rsum1;
    int b = bh >> 2, h = bh & 3;
#pragma unroll
    for (int jo = 0; jo < 8; jo++) {
        int sc = 8*jo + 2*tg;
        *reinterpret_cast<u32*>(&g_ao[(long)(b*T_ + r0)*DM + h*HS + sc]) =
            packbf(o[jo][0]*inv0, o[jo][1]*inv0);
        *reinterpret_cast<u32*>(&g_ao[(long)(b*T_ + r0 + 8)*DM + h*HS + sc]) =
            packbf(o[jo][2]*inv1, o[jo][3]*inv1);
    }
}

// ---------------- K4: out projection + bias + residual, double-buffered + ldmatrix ----------------
__global__ __launch_bounds__(256) void out_kernel(const float* __restrict__ bo,
                                                  const float* __restrict__ resid,
                                                  float* __restrict__ out) {
    extern __shared__ __align__(16) bf16 dsm[];
    bf16 (*As)[LDA] = reinterpret_cast<bf16(*)[LDA]>(dsm);
    bf16 (*Bs)[LDA] = reinterpret_cast<bf16(*)[LDA]>(dsm + 2*128*LDA);
    int m0 = blockIdx.x * 128, n0 = blockIdx.y * 128;
    const bf16* A = g_ao;
    const bf16* W = g_Wt[4];
    int tid = threadIdx.x;
    int wid = tid >> 5, lane = tid & 31;
    int wm = wid & 3, wn = wid >> 2;
    int g = lane >> 2, tg = lane & 3;
    int arow = AROW(lane), acol = ACOL(lane);
    int brow = BROW(lane), bcol = BCOL(lane);

    auto stage = [&](int buf, int k0) {
#pragma unroll
        for (int i = 0; i < 4; i++) {
            int cid = tid + 256*i;
            int row = cid >> 3, seg = cid & 7;
            cpasync16(&As[buf*128 + row][seg*8], A + (size_t)(m0 + row)*DM + k0 + seg*8);
            cpasync16(&Bs[buf*128 + row][seg*8], W + (size_t)(n0 + row)*DM + k0 + seg*8);
        }
        CP_COMMIT();
    };

    float acc[2][8][4] = {};
    stage(0, 0);
    for (int c = 0; c < DM/KCH; c++) {
        if (c + 1 < DM/KCH) { stage((c+1) & 1, (c+1)*KCH); CP_WAIT(1); }
        else                { CP_WAIT(0); }
        __syncthreads();
        int bo_ = (c & 1) * 128;
#pragma unroll
        for (int ks = 0; ks < KCH/16; ks++) {
            u32 a[2][4];
#pragma unroll
            for (int mt = 0; mt < 2; mt++)
                ldsm4(a[mt], s2u(&As[bo_ + wm*32 + mt*16 + arow][ks*16 + acol]));
#pragma unroll
            for (int ntp = 0; ntp < 4; ntp++) {
                u32 r[4];
                ldsm4(r, s2u(&Bs[bo_ + wn*64 + ntp*16 + brow][ks*16 + bcol]));
                mma16816(acc[0][2*ntp],   a[0], &r[0]);
                mma16816(acc[0][2*ntp+1], a[0], &r[2]);
                mma16816(acc[1][2*ntp],   a[1], &r[0]);
                mma16816(acc[1][2*ntp+1], a[1], &r[2]);
            }
        }
        __syncthreads();
    }
#pragma unroll
    for (int mt = 0; mt < 2; mt++)
#pragma unroll
    for (int nt = 0; nt < 8; nt++)
#pragma unroll
    for (int e = 0; e < 4; e++) {
        int rr = m0 + wm*32 + mt*16 + g + ((e >= 2) ? 8 : 0);
        int cc = n0 + wn*64 + nt*8 + 2*tg + (e & 1);
        out[(size_t)rr*DM + cc] = acc[mt][nt][e] + bo[cc] + resid[(size_t)rr*DM + cc];
    }
}

// ---------------- launch ----------------
extern "C" void kernel_launch(void* const* d_in, const int* in_sizes, int n_in,
                              void* d_out, int out_size) {
    const float* inputs  = (const float*)d_in[0];
    const float* pos_enc = (const float*)d_in[1];
    const float* gamma   = (const float*)d_in[2];
    const float* beta    = (const float*)d_in[3];
    const float* Wq      = (const float*)d_in[4];
    const float* bq      = (const float*)d_in[5];
    const float* Wk      = (const float*)d_in[6];
    const float* bk      = (const float*)d_in[7];
    const float* Wv      = (const float*)d_in[8];
    const float* bv      = (const float*)d_in[9];
    const float* Wp      = (const float*)d_in[10];
    const float* Wo      = (const float*)d_in[11];
    const float* bo      = (const float*)d_in[12];
    const float* pbu     = (const float*)d_in[13];
    const float* pbv     = (const float*)d_in[14];
    float* out = (float*)d_out;

    static bool attr_set = false;
    if (!attr_set) {
        cudaFuncSetAttribute(proj_kernel, cudaFuncAttributeMaxDynamicSharedMemorySize, GEMM_SMEM);
        cudaFuncSetAttribute(out_kernel,  cudaFuncAttributeMaxDynamicSharedMemorySize, GEMM_SMEM);
        attr_set = true;
    }

    ln_kernel<<<BT/8, 256>>>(inputs, gamma, beta);
    cvt_pe_kernel<<<(BT*DM + 1023)/1024, 1024>>>(pos_enc);
    wt_kernel<<<(5*DM*DM + 255)/256, 256>>>(Wq, Wk, Wv, Wp, Wo);
    proj_kernel<<<dim3(BT/128, DM/128, 4), 256, GEMM_SMEM>>>(bq, bk, bv, pbu, pbv);
    pos_kernel<<<dim3(T_/128, T_/128, BH), 256>>>();
    attn_kernel<<<dim3(T_/128, BH), 256>>>();
    out_kernel<<<dim3(BT/128, DM/128), 256, GEMM_SMEM>>>(bo, inputs, out);
}